// round 14
// baseline (speedup 1.0000x reference)
#include <cuda_runtime.h>
#include <cuda_bf16.h>

#define NG 1024
#define HH 768
#define WW 768
#define TPX 16   // pixels per thread along w (8 f32x2 pairs)

// Per-gaussian coefficients, 16 floats (4 x float4):
// q0: [0]=mx [1]=-my [2]=Dm2 [3]=A
// q1: [4]=B  [5]=Bd  [6]=Dmd [7]=Dd2
// q2: [8]=s  [9]=s3  [10]=s4 [11]=wb
// q3: [12]=wr [13]=wg [14..15]=pad
// A,B,D pre-scaled by -0.5*log2(e); delta=1/767; Bd=B*delta, Dmd=Dm*delta,
// Dd2=D*delta^2; s = 2^(2*D*delta^2)
__device__ __align__(16) float g_coef[NG * 16];

typedef unsigned long long u64;

__device__ __forceinline__ u64 pk2(float lo, float hi) {
    u64 d; asm("mov.b64 %0, {%1, %2};" : "=l"(d) : "f"(lo), "f"(hi)); return d;
}
__device__ __forceinline__ void upk2(u64 v, float& lo, float& hi) {
    asm("mov.b64 {%0, %1}, %2;" : "=f"(lo), "=f"(hi) : "l"(v));
}
__device__ __forceinline__ u64 fma2(u64 a, u64 b, u64 c) {
    u64 d; asm("fma.rn.f32x2 %0, %1, %2, %3;" : "=l"(d) : "l"(a), "l"(b), "l"(c)); return d;
}
__device__ __forceinline__ u64 mul2(u64 a, u64 b) {
    u64 d; asm("mul.rn.f32x2 %0, %1, %2;" : "=l"(d) : "l"(a), "l"(b)); return d;
}
__device__ __forceinline__ float ex2f(float a) {
    float v; asm("ex2.approx.ftz.f32 %0, %1;" : "=f"(v) : "f"(a)); return v;
}

__global__ void prep_kernel(const float* __restrict__ means,
                            const float* __restrict__ cov,
                            const float* __restrict__ colors) {
    int n = blockIdx.x * blockDim.x + threadIdx.x;
    if (n >= NG) return;
    float mx = means[2 * n + 0];
    float my = means[2 * n + 1];
    float a = cov[4 * n + 0];
    float b = cov[4 * n + 1];
    float c = cov[4 * n + 2];
    float d = cov[4 * n + 3];
    float det = a * d - b * c;
    float ia  = d / det;
    float ibc = (-b - c) / det;   // ib + ic
    float idd = a / det;
    const float k = -0.72134752044448170368f;  // -0.5 * log2(e)
    float A = k * ia;
    float B = k * ibc;
    float D = k * idd;
    float Dm  = -2.0f * D * my;
    float Dm2 = D * my * my;
    const float delta = 1.0f / 767.0f;
    float Bd  = B * delta;
    float Dmd = Dm * delta;
    float Dd2 = D * delta * delta;
    float s   = exp2f(2.0f * Dd2);
    float s3  = s * s * s;
    float s4  = s * s3;
    float cr = colors[4 * n + 0];
    float cg = colors[4 * n + 1];
    float cb = colors[4 * n + 2];
    float al = colors[4 * n + 3];
    float wr = al / (1.0f + __expf(-cr));
    float wg = al / (1.0f + __expf(-cg));
    float wb = al / (1.0f + __expf(-cb));
    float* o = g_coef + 16 * n;
    o[0]  = mx;  o[1]  = -my; o[2]  = Dm2; o[3]  = A;
    o[4]  = B;   o[5]  = Bd;  o[6]  = Dmd; o[7]  = Dd2;
    o[8]  = s;   o[9]  = s3;  o[10] = s4;  o[11] = wb;
    o[12] = wr;  o[13] = wg;  o[14] = 0.f; o[15] = 0.f;
}

// Block: 128 threads = 8 segments (16 px each, 128 px wide) x 16 rows.
// Grid (768/128, 768/16) = (6, 48) = 288 blocks, 2 CTAs/SM. Dynamic smem 64KB.
__global__ __launch_bounds__(128)
void render_kernel(float* __restrict__ out) {
    extern __shared__ float shf[];          // 64 KB, 16 floats per gaussian
    u64* shu = (u64*)shf;
    {
        const float4* gc = (const float4*)g_coef;
        float4* sf = (float4*)shf;
        #pragma unroll 8
        for (int i = threadIdx.x; i < NG * 4; i += 128) sf[i] = gc[i];
    }
    __syncthreads();

    int tid = threadIdx.x;
    int seg = tid & 7;     // 0..7 -> which 16-pixel segment
    int row = tid >> 3;    // 0..15 -> row within tile
    int h  = blockIdx.y * 16 + row;
    int w0 = blockIdx.x * 128 + seg * TPX;

    const float inv = 1.0f / 767.0f;   // delta
    float x    = (float)h * inv;
    float u0   = (float)w0;            // integer column coordinate
    float u0sq = u0 * u0;
    float u2p1 = 2.0f * u0 + 1.0f;

    u64 ar2[TPX / 2], ag2[TPX / 2], ab2[TPX / 2];
    #pragma unroll
    for (int kk = 0; kk < TPX / 2; kk++) { ar2[kk] = 0ull; ag2[kk] = 0ull; ab2[kk] = 0ull; }

    #pragma unroll 4
    for (int n = 0; n < NG; n++) {
        const float4* q = (const float4*)(shf + 16 * n);
        float4 q0 = q[0];                 // mx, -my, Dm2, A
        float4 q1 = q[1];                 // B, Bd, Dmd, Dd2
        float4 q2 = q[2];                 // s, s3, s4, wb
        u64 wrg   = shu[8 * n + 6];       // {wr, wg}
        float mx = q0.x, nmy = q0.y, Dm2 = q0.z, A = q0.w;
        float B  = q1.x, Bd  = q1.y, Dmd = q1.z, Dd2 = q1.w;

        // Hoist per (gaussian, row), u-parametrized:
        // arg(u) = e0 + Edu*u + Dd2*u^2
        float dx  = x - mx;
        float t   = A * dx;
        float c1  = B * dx;
        float c0  = fmaf(t, dx, Dm2);
        float e0  = fmaf(nmy, c1, c0);
        float Edu = fmaf(Bd, dx, Dmd);

        float arg0 = fmaf(Edu, u0, fmaf(Dd2, u0sq, e0));
        float rarg = fmaf(Dd2, u2p1, Edu);
        float v0 = ex2f(arg0);
        float r0 = ex2f(rarg);

        float v1  = v0 * r0;
        float r0q = r0 * r0;
        u64 V  = pk2(v0, v1);
        u64 P  = mul2(pk2(r0q, r0q), pk2(q2.x, q2.y));   // {r0^2*s, r0^2*s^3}
        u64 S4 = pk2(q2.z, q2.z);

        float wr, wg;
        upk2(wrg, wr, wg);
        u64 wr2 = pk2(wr, wr);
        u64 wg2 = pk2(wg, wg);
        u64 wb2 = pk2(q2.w, q2.w);

        #pragma unroll
        for (int kk = 0; kk < TPX / 2; kk++) {
            ar2[kk] = fma2(V, wr2, ar2[kk]);
            ag2[kk] = fma2(V, wg2, ag2[kk]);
            ab2[kk] = fma2(V, wb2, ab2[kk]);
            if (kk < TPX / 2 - 1) {
                V = mul2(V, P);
                if (kk < TPX / 2 - 2) P = mul2(P, S4);
            }
        }
    }

    // Unpack and store: 48 contiguous floats per thread -> 12 x STG.128
    float r[TPX], g[TPX], b[TPX];
    #pragma unroll
    for (int kk = 0; kk < TPX / 2; kk++) {
        upk2(ar2[kk], r[2 * kk], r[2 * kk + 1]);
        upk2(ag2[kk], g[2 * kk], g[2 * kk + 1]);
        upk2(ab2[kk], b[2 * kk], b[2 * kk + 1]);
    }
    float buf[TPX * 3];
    #pragma unroll
    for (int j = 0; j < TPX; j++) {
        buf[3 * j + 0] = r[j];
        buf[3 * j + 1] = g[j];
        buf[3 * j + 2] = b[j];
    }
    float4* o = (float4*)(out + ((size_t)h * WW + w0) * 3);
    #pragma unroll
    for (int q = 0; q < TPX * 3 / 4; q++) o[q] = ((float4*)buf)[q];
}

extern "C" void kernel_launch(void* const* d_in, const int* in_sizes, int n_in,
                              void* d_out, int out_size) {
    const float* means  = (const float*)d_in[0];
    const float* cov    = (const float*)d_in[1];
    const float* colors = (const float*)d_in[2];
    float* out = (float*)d_out;

    static int configured = 0;
    if (!configured) {
        cudaFuncSetAttribute(render_kernel,
                             cudaFuncAttributeMaxDynamicSharedMemorySize, NG * 16 * 4);
        configured = 1;
    }

    prep_kernel<<<4, 256>>>(means, cov, colors);
    dim3 grid(WW / 128, HH / 16);
    render_kernel<<<grid, 128, NG * 16 * 4>>>(out);
}